// round 5
// baseline (speedup 1.0000x reference)
#include <cuda_runtime.h>
#include <math.h>
#include <stdint.h>

// Problem constants
#define BATCH 2
#define NPTS 1024
#define NUM_BINS 22
#define TDIM 16
#define TSTRIDE 20           // padded row stride (floats) to reduce LDS bank conflicts
#define MAX_DIST 40.0f
#define LN_EPS 1e-5f

// ---------------------------------------------------------------------------
// Single fused kernel. One block = (j-tile of 256) x i x batch, grid 8192.
//   Prologue (threads 0..21): build 22x16 table rows in smem:
//       T[bin] = relu(LN(W[bin]+b)*gamma+beta)   (no separate launch)
//   Phase A (all 256 threads): per-j bin offset + scale into smem.
//   Phase B: 4 lanes/pair: LDS.64 (off,s) + LDS.128 table row chunk,
//            2 packed f32x2 muls, STG.128 with .cs (evict-first) policy.
// ---------------------------------------------------------------------------
__global__ __launch_bounds__(256)
void encode_kernel(const float* __restrict__ coords,
                   const float* __restrict__ conf,
                   const float* __restrict__ W,
                   const float* __restrict__ bb,
                   const float* __restrict__ gamma,
                   const float* __restrict__ beta,
                   float* __restrict__ out) {
    __shared__ float  sT[NUM_BINS * TSTRIDE];
    __shared__ float2 sP[256];    // (row byte-offset, scale) per local j

    const int tid   = threadIdx.x;
    const int i     = blockIdx.y;
    const int batch = blockIdx.z;
    const int j_base = blockIdx.x * 256;

    // ---- Prologue: build table row for bin = tid (threads 0..21) ----
    if (tid < NUM_BINS) {
        float h[TDIM];
        float sum = 0.0f;
#pragma unroll
        for (int d = 0; d < TDIM; ++d) {
            h[d] = W[tid * TDIM + d] + bb[d];
            sum += h[d];
        }
        float mu = sum * (1.0f / TDIM);
        float var = 0.0f;
#pragma unroll
        for (int d = 0; d < TDIM; ++d) {
            float c = h[d] - mu;
            var += c * c;
        }
        var *= (1.0f / TDIM);
        float inv = rsqrtf(var + LN_EPS);
#pragma unroll
        for (int d = 0; d < TDIM; ++d) {
            float v = (h[d] - mu) * inv * gamma[d] + beta[d];
            sT[tid * TSTRIDE + d] = fmaxf(v, 0.0f);
        }
    }

    // ---- Phase A: per-j precompute (one thread per j) ----
    {
        const float* ci_ptr = coords + ((size_t)batch * NPTS + i) * 3;
        const float xi = ci_ptr[0], yi = ci_ptr[1], zi = ci_ptr[2];
        const float ci = conf[batch * NPTS + i];

        const int j = j_base + tid;
        const float* cj_ptr = coords + ((size_t)batch * NPTS + j) * 3;
        const float dx = xi - cj_ptr[0];
        const float dy = yi - cj_ptr[1];
        const float dz = zi - cj_ptr[2];
        const float cj = conf[batch * NPTS + j];

        const float dist = sqrtf(fmaf(dx, dx, fmaf(dy, dy, fmaf(dz, dz, 1e-8f))));
        const float inv_w = (float)(NUM_BINS - 1) / MAX_DIST;  // 21/40

        int bin;
        if (ci > 0.0f && cj > 0.0f) {
            bin = (int)(dist * inv_w) + 1;          // #edges strictly below dist
            bin = (bin > NUM_BINS - 2) ? (NUM_BINS - 2) : bin;
        } else {
            bin = NUM_BINS - 1;
        }
        sP[tid] = make_float2(__int_as_float(bin * (TSTRIDE * 4)),
                              fminf(ci, cj));
    }
    __syncthreads();

    // ---- Phase B: gather + scale + store ----
    const int p = tid >> 2;   // pair slot within 64
    const int k = tid & 3;    // which float4 of the 16-vector

    float* optr = out + (((size_t)batch * NPTS + i) * NPTS + j_base + p) * TDIM + k * 4;
    const char* tbase = (const char*)sT + k * 16;

#pragma unroll
    for (int it = 0; it < 4; ++it) {
        const float2 pk = sP[it * 64 + p];      // broadcast within 4-lane group
        const int   off = __float_as_int(pk.x);
        const float s   = pk.y;

        float4 v = *(const float4*)(tbase + off);

        // packed f32x2 multiplies
        uint64_t lo, hi, sv, rlo, rhi;
        asm("mov.b64 %0, {%1, %2};" : "=l"(sv) : "f"(s), "f"(s));
        asm("mov.b64 %0, {%1, %2};" : "=l"(lo) : "f"(v.x), "f"(v.y));
        asm("mov.b64 %0, {%1, %2};" : "=l"(hi) : "f"(v.z), "f"(v.w));
        asm("mul.rn.f32x2 %0, %1, %2;" : "=l"(rlo) : "l"(lo), "l"(sv));
        asm("mul.rn.f32x2 %0, %1, %2;" : "=l"(rhi) : "l"(hi), "l"(sv));
        float rx, ry, rz, rw;
        asm("mov.b64 {%0, %1}, %2;" : "=f"(rx), "=f"(ry) : "l"(rlo));
        asm("mov.b64 {%0, %1}, %2;" : "=f"(rz), "=f"(rw) : "l"(rhi));

        // evict-first store: drain dirty lines to DRAM eagerly
        asm volatile("st.global.cs.v4.f32 [%0], {%1, %2, %3, %4};"
                     :: "l"(optr + (size_t)it * 64 * TDIM),
                        "f"(rx), "f"(ry), "f"(rz), "f"(rw)
                     : "memory");
    }
}

// ---------------------------------------------------------------------------
// Launch: single kernel, single graph node.
// ---------------------------------------------------------------------------
extern "C" void kernel_launch(void* const* d_in, const int* in_sizes, int n_in,
                              void* d_out, int out_size) {
    const float* coords = (const float*)d_in[0];  // (B,N,3)
    const float* conf   = (const float*)d_in[1];  // (B,N)
    const float* W      = (const float*)d_in[2];  // (22,16)
    const float* b      = (const float*)d_in[3];  // (16,)
    const float* gamma  = (const float*)d_in[4];  // (16,)
    const float* beta   = (const float*)d_in[5];  // (16,)
    float* out = (float*)d_out;                   // (B,N,N,16)

    dim3 grid(NPTS / 256, NPTS, BATCH);
    encode_kernel<<<grid, 256>>>(coords, conf, W, b, gamma, beta, out);
}

// round 6
// speedup vs baseline: 1.0010x; 1.0010x over previous
#include <cuda_runtime.h>
#include <math.h>
#include <stdint.h>

// Problem constants
#define BATCH 2
#define NPTS 1024
#define NUM_BINS 22
#define TDIM 16
#define TSTRIDE 20           // padded row stride (floats) to reduce LDS bank conflicts
#define MAX_DIST 40.0f
#define LN_EPS 1e-5f

// ---------------------------------------------------------------------------
// Single fused kernel (one graph node). One block = (j-tile of 256) x i x batch.
//   Prologue (threads 0..21): build 22x16 table rows in smem:
//       T[bin] = relu(LN(W[bin]+b)*gamma+beta)
//     runs concurrently with Phase A of the other 7 warps.
//   Phase A (all 256 threads): per-j (bin byte-offset, scale) into smem.
//   Phase B: 4 lanes/pair: LDS.64 (off,s broadcast) + LDS.128 table chunk,
//            2 packed f32x2 muls, default-policy STG.128.
// ---------------------------------------------------------------------------
__global__ __launch_bounds__(256)
void encode_kernel(const float* __restrict__ coords,
                   const float* __restrict__ conf,
                   const float* __restrict__ W,
                   const float* __restrict__ bb,
                   const float* __restrict__ gamma,
                   const float* __restrict__ beta,
                   float* __restrict__ out) {
    __shared__ float  sT[NUM_BINS * TSTRIDE];
    __shared__ float2 sP[256];    // (row byte-offset, scale) per local j

    const int tid   = threadIdx.x;
    const int i     = blockIdx.y;
    const int batch = blockIdx.z;
    const int j_base = blockIdx.x * 256;

    // ---- Prologue: build table row for bin = tid (threads 0..21) ----
    if (tid < NUM_BINS) {
        float h[TDIM];
        float sum = 0.0f;
#pragma unroll
        for (int d = 0; d < TDIM; ++d) {
            h[d] = W[tid * TDIM + d] + bb[d];
            sum += h[d];
        }
        float mu = sum * (1.0f / TDIM);
        float var = 0.0f;
#pragma unroll
        for (int d = 0; d < TDIM; ++d) {
            float c = h[d] - mu;
            var += c * c;
        }
        var *= (1.0f / TDIM);
        float inv = rsqrtf(var + LN_EPS);
#pragma unroll
        for (int d = 0; d < TDIM; ++d) {
            float v = (h[d] - mu) * inv * gamma[d] + beta[d];
            sT[tid * TSTRIDE + d] = fmaxf(v, 0.0f);
        }
    }

    // ---- Phase A: per-j precompute (one thread per j) ----
    {
        const float* ci_ptr = coords + ((size_t)batch * NPTS + i) * 3;
        const float xi = ci_ptr[0], yi = ci_ptr[1], zi = ci_ptr[2];
        const float ci = conf[batch * NPTS + i];

        const int j = j_base + tid;
        const float* cj_ptr = coords + ((size_t)batch * NPTS + j) * 3;
        const float dx = xi - cj_ptr[0];
        const float dy = yi - cj_ptr[1];
        const float dz = zi - cj_ptr[2];
        const float cj = conf[batch * NPTS + j];

        const float dist = sqrtf(fmaf(dx, dx, fmaf(dy, dy, fmaf(dz, dz, 1e-8f))));
        const float inv_w = (float)(NUM_BINS - 1) / MAX_DIST;  // 21/40

        int bin;
        if (ci > 0.0f && cj > 0.0f) {
            bin = (int)(dist * inv_w) + 1;          // #edges strictly below dist
            bin = (bin > NUM_BINS - 2) ? (NUM_BINS - 2) : bin;
        } else {
            bin = NUM_BINS - 1;
        }
        sP[tid] = make_float2(__int_as_float(bin * (TSTRIDE * 4)),
                              fminf(ci, cj));
    }
    __syncthreads();

    // ---- Phase B: gather + scale + store ----
    const int p = tid >> 2;   // pair slot within 64
    const int k = tid & 3;    // which float4 of the 16-vector

    float* optr = out + (((size_t)batch * NPTS + i) * NPTS + j_base + p) * TDIM + k * 4;
    const char* tbase = (const char*)sT + k * 16;

#pragma unroll
    for (int it = 0; it < 4; ++it) {
        const float2 pk = sP[it * 64 + p];      // broadcast within 4-lane group
        const int   off = __float_as_int(pk.x);
        const float s   = pk.y;

        float4 v = *(const float4*)(tbase + off);

        // packed f32x2 multiplies: 2 instructions instead of 4
        uint64_t lo, hi, sv, rlo, rhi;
        asm("mov.b64 %0, {%1, %2};" : "=l"(sv) : "f"(s), "f"(s));
        asm("mov.b64 %0, {%1, %2};" : "=l"(lo) : "f"(v.x), "f"(v.y));
        asm("mov.b64 %0, {%1, %2};" : "=l"(hi) : "f"(v.z), "f"(v.w));
        asm("mul.rn.f32x2 %0, %1, %2;" : "=l"(rlo) : "l"(lo), "l"(sv));
        asm("mul.rn.f32x2 %0, %1, %2;" : "=l"(rhi) : "l"(hi), "l"(sv));
        float4 r;
        asm("mov.b64 {%0, %1}, %2;" : "=f"(r.x), "=f"(r.y) : "l"(rlo));
        asm("mov.b64 {%0, %1}, %2;" : "=f"(r.z), "=f"(r.w) : "l"(rhi));

        *(float4*)(optr + (size_t)it * 64 * TDIM) = r;   // default cache policy
    }
}

// ---------------------------------------------------------------------------
// Launch: single kernel, single graph node.
// ---------------------------------------------------------------------------
extern "C" void kernel_launch(void* const* d_in, const int* in_sizes, int n_in,
                              void* d_out, int out_size) {
    const float* coords = (const float*)d_in[0];  // (B,N,3)
    const float* conf   = (const float*)d_in[1];  // (B,N)
    const float* W      = (const float*)d_in[2];  // (22,16)
    const float* b      = (const float*)d_in[3];  // (16,)
    const float* gamma  = (const float*)d_in[4];  // (16,)
    const float* beta   = (const float*)d_in[5];  // (16,)
    float* out = (float*)d_out;                   // (B,N,N,16)

    dim3 grid(NPTS / 256, NPTS, BATCH);
    encode_kernel<<<grid, 256>>>(coords, conf, W, b, gamma, beta, out);
}

// round 7
// speedup vs baseline: 1.0609x; 1.0598x over previous
#include <cuda_runtime.h>
#include <math.h>
#include <stdint.h>

// Problem constants
#define BATCH 2
#define NPTS 1024
#define NUM_BINS 22
#define TDIM 16
#define TSTRIDE 20           // padded table row stride (floats) for LDS conflicts
#define MAX_DIST 40.0f
#define LN_EPS 1e-5f

#define BLOCK 512            // threads per block; block covers 512 j's

// ---------------------------------------------------------------------------
// Single fused kernel (one graph node). Grid (N/512, N, B) = 4096 blocks.
//   Prologue (threads 0..21): build table row T[bin]=relu(LN(W[bin]+b)*g+be)
//     using vectorized float4 loads (16 LDG.128, one latency exposure).
//   Phase A (512 threads): per-j (bin byte-offset, scale) into smem.
//   Phase B: 4 lanes/pair; LDS.64 broadcast + LDS.128 table chunk,
//            2 packed f32x2 muls, default-policy STG.128.
// ---------------------------------------------------------------------------
__global__ __launch_bounds__(BLOCK)
void encode_kernel(const float* __restrict__ coords,
                   const float* __restrict__ conf,
                   const float* __restrict__ W,
                   const float* __restrict__ bb,
                   const float* __restrict__ gamma,
                   const float* __restrict__ beta,
                   float* __restrict__ out) {
    __shared__ float  sT[NUM_BINS * TSTRIDE];   // 1760 B
    __shared__ float2 sP[BLOCK];                // 4 KB

    const int tid    = threadIdx.x;
    const int i      = blockIdx.y;
    const int batch  = blockIdx.z;
    const int j_base = blockIdx.x * BLOCK;

    // ---- Prologue: vectorized table build (threads 0..21) ----
    if (tid < NUM_BINS) {
        const float4* W4 = (const float4*)(W + tid * TDIM);
        float4 w[4];
        w[0] = W4[0]; w[1] = W4[1]; w[2] = W4[2]; w[3] = W4[3];
        float4 bv[4], gv[4], ev[4];
#pragma unroll
        for (int q = 0; q < 4; ++q) {
            bv[q] = ((const float4*)bb)[q];
            gv[q] = ((const float4*)gamma)[q];
            ev[q] = ((const float4*)beta)[q];
        }
        float h[TDIM];
#pragma unroll
        for (int q = 0; q < 4; ++q) {
            h[4*q+0] = ((const float*)&w[q])[0] + ((const float*)&bv[q])[0];
            h[4*q+1] = ((const float*)&w[q])[1] + ((const float*)&bv[q])[1];
            h[4*q+2] = ((const float*)&w[q])[2] + ((const float*)&bv[q])[2];
            h[4*q+3] = ((const float*)&w[q])[3] + ((const float*)&bv[q])[3];
        }
        float sum = 0.0f;
#pragma unroll
        for (int d = 0; d < TDIM; ++d) sum += h[d];
        const float mu = sum * (1.0f / TDIM);
        float var = 0.0f;
#pragma unroll
        for (int d = 0; d < TDIM; ++d) {
            const float c = h[d] - mu;
            var += c * c;
        }
        var *= (1.0f / TDIM);
        const float inv = rsqrtf(var + LN_EPS);
#pragma unroll
        for (int d = 0; d < TDIM; ++d) {
            const float g = ((const float*)&gv[d >> 2])[d & 3];
            const float e = ((const float*)&ev[d >> 2])[d & 3];
            const float v = (h[d] - mu) * inv * g + e;
            sT[tid * TSTRIDE + d] = fmaxf(v, 0.0f);
        }
    }

    // ---- Phase A: per-j precompute (one thread per j) ----
    {
        const float* ci_ptr = coords + ((size_t)batch * NPTS + i) * 3;
        const float xi = ci_ptr[0], yi = ci_ptr[1], zi = ci_ptr[2];
        const float ci = conf[batch * NPTS + i];

        const int j = j_base + tid;
        const float* cj_ptr = coords + ((size_t)batch * NPTS + j) * 3;
        const float dx = xi - cj_ptr[0];
        const float dy = yi - cj_ptr[1];
        const float dz = zi - cj_ptr[2];
        const float cj = conf[batch * NPTS + j];

        const float dist = sqrtf(fmaf(dx, dx, fmaf(dy, dy, fmaf(dz, dz, 1e-8f))));
        const float inv_w = (float)(NUM_BINS - 1) / MAX_DIST;  // 21/40

        int bin;
        if (ci > 0.0f && cj > 0.0f) {
            bin = (int)(dist * inv_w) + 1;          // #edges strictly below dist
            bin = (bin > NUM_BINS - 2) ? (NUM_BINS - 2) : bin;
        } else {
            bin = NUM_BINS - 1;
        }
        sP[tid] = make_float2(__int_as_float(bin * (TSTRIDE * 4)),
                              fminf(ci, cj));
    }
    __syncthreads();

    // ---- Phase B: gather + scale + store ----
    const int p = tid >> 2;   // pair slot within 128
    const int k = tid & 3;    // which float4 of the 16-vector

    float* optr = out + (((size_t)batch * NPTS + i) * NPTS + j_base + p) * TDIM + k * 4;
    const char* tbase = (const char*)sT + k * 16;

#pragma unroll
    for (int it = 0; it < 4; ++it) {
        const float2 pk = sP[it * 128 + p];     // broadcast within 4-lane group
        const int   off = __float_as_int(pk.x);
        const float s   = pk.y;

        float4 v = *(const float4*)(tbase + off);

        // packed f32x2 multiplies: 2 instructions instead of 4
        uint64_t lo, hi, sv, rlo, rhi;
        asm("mov.b64 %0, {%1, %2};" : "=l"(sv) : "f"(s), "f"(s));
        asm("mov.b64 %0, {%1, %2};" : "=l"(lo) : "f"(v.x), "f"(v.y));
        asm("mov.b64 %0, {%1, %2};" : "=l"(hi) : "f"(v.z), "f"(v.w));
        asm("mul.rn.f32x2 %0, %1, %2;" : "=l"(rlo) : "l"(lo), "l"(sv));
        asm("mul.rn.f32x2 %0, %1, %2;" : "=l"(rhi) : "l"(hi), "l"(sv));
        float4 r;
        asm("mov.b64 {%0, %1}, %2;" : "=f"(r.x), "=f"(r.y) : "l"(rlo));
        asm("mov.b64 {%0, %1}, %2;" : "=f"(r.z), "=f"(r.w) : "l"(rhi));

        *(float4*)(optr + (size_t)it * 128 * TDIM) = r;  // default cache policy
    }
}

// ---------------------------------------------------------------------------
// Launch: single kernel, single graph node.
// ---------------------------------------------------------------------------
extern "C" void kernel_launch(void* const* d_in, const int* in_sizes, int n_in,
                              void* d_out, int out_size) {
    const float* coords = (const float*)d_in[0];  // (B,N,3)
    const float* conf   = (const float*)d_in[1];  // (B,N)
    const float* W      = (const float*)d_in[2];  // (22,16)
    const float* b      = (const float*)d_in[3];  // (16,)
    const float* gamma  = (const float*)d_in[4];  // (16,)
    const float* beta   = (const float*)d_in[5];  // (16,)
    float* out = (float*)d_out;                   // (B,N,N,16)

    dim3 grid(NPTS / BLOCK, NPTS, BATCH);
    encode_kernel<<<grid, BLOCK>>>(coords, conf, W, b, gamma, beta, out);
}

// round 9
// speedup vs baseline: 1.0832x; 1.0211x over previous
#include <cuda_runtime.h>
#include <math.h>
#include <stdint.h>

// Problem constants
#define BATCH 2
#define NPTS 1024
#define NUM_BINS 22
#define TDIM 16
#define TSTRIDE 20           // padded table row stride (floats) for LDS conflicts
#define MAX_DIST 40.0f
#define LN_EPS 1e-5f

// Precomputed per-bin rows: T[bin][d] = relu(LN(W[bin]+b)*gamma+beta)
__device__ float g_table[NUM_BINS * TSTRIDE];

// ---------------------------------------------------------------------------
// Kernel 1: build the 22x16 table. One warp, one thread/bin. Triggers the
// dependent encode kernel as soon as the table is globally visible.
// ---------------------------------------------------------------------------
__global__ void build_table_kernel(const float* __restrict__ W,
                                   const float* __restrict__ b,
                                   const float* __restrict__ gamma,
                                   const float* __restrict__ beta) {
    int bin = threadIdx.x;
    if (bin < NUM_BINS) {
        float h[TDIM];
        float sum = 0.0f;
#pragma unroll
        for (int d = 0; d < TDIM; ++d) {
            h[d] = W[bin * TDIM + d] + b[d];
            sum += h[d];
        }
        float mu = sum * (1.0f / TDIM);
        float var = 0.0f;
#pragma unroll
        for (int d = 0; d < TDIM; ++d) {
            float c = h[d] - mu;
            var += c * c;
        }
        var *= (1.0f / TDIM);
        float inv = rsqrtf(var + LN_EPS);
#pragma unroll
        for (int d = 0; d < TDIM; ++d) {
            float v = (h[d] - mu) * inv * gamma[d] + beta[d];
            g_table[bin * TSTRIDE + d] = fmaxf(v, 0.0f);
        }
    }
    __threadfence();                               // make table globally visible
    cudaTriggerProgrammaticLaunchCompletion();     // release dependent launch
}

// ---------------------------------------------------------------------------
// Kernel 2 (R2's proven body, reordered for PDL):
//   Phase A: per-j (bin byte-offset, scale) into smem  [table-independent]
//   cudaGridDependencySynchronize()                     [wait for kernel 1]
//   table -> smem, __syncthreads
//   Phase B: 4 lanes/pair: LDS.64 broadcast + LDS.128 gather,
//            2 packed f32x2 muls, STG.128.
// ---------------------------------------------------------------------------
__global__ __launch_bounds__(256)
void encode_kernel(const float* __restrict__ coords,
                   const float* __restrict__ conf,
                   float* __restrict__ out) {
    __shared__ float  sT[NUM_BINS * TSTRIDE];
    __shared__ float2 sP[256];    // (row byte-offset, scale) per local j

    const int tid    = threadIdx.x;
    const int i      = blockIdx.y;
    const int batch  = blockIdx.z;
    const int j_base = blockIdx.x * 256;

    // ---- Phase A: per-j precompute (one thread per j; no table needed) ----
    {
        const float* ci_ptr = coords + ((size_t)batch * NPTS + i) * 3;
        const float xi = ci_ptr[0], yi = ci_ptr[1], zi = ci_ptr[2];
        const float ci = conf[batch * NPTS + i];

        const int j = j_base + tid;
        const float* cj_ptr = coords + ((size_t)batch * NPTS + j) * 3;
        const float dx = xi - cj_ptr[0];
        const float dy = yi - cj_ptr[1];
        const float dz = zi - cj_ptr[2];
        const float cj = conf[batch * NPTS + j];

        const float dist = sqrtf(fmaf(dx, dx, fmaf(dy, dy, fmaf(dz, dz, 1e-8f))));
        const float inv_w = (float)(NUM_BINS - 1) / MAX_DIST;  // 21/40

        int bin;
        if (ci > 0.0f && cj > 0.0f) {
            bin = (int)(dist * inv_w) + 1;          // #edges strictly below dist
            bin = (bin > NUM_BINS - 2) ? (NUM_BINS - 2) : bin;
        } else {
            bin = NUM_BINS - 1;
        }
        sP[tid] = make_float2(__int_as_float(bin * (TSTRIDE * 4)),
                              fminf(ci, cj));
    }

    // ---- Wait for build_table_kernel, then pull table into smem ----
    cudaGridDependencySynchronize();
    for (int t = tid; t < NUM_BINS * TSTRIDE; t += 256) sT[t] = g_table[t];
    __syncthreads();

    // ---- Phase B: gather + scale + store ----
    const int p = tid >> 2;   // pair slot within 64
    const int k = tid & 3;    // which float4 of the 16-vector

    float* optr = out + (((size_t)batch * NPTS + i) * NPTS + j_base + p) * TDIM + k * 4;
    const char* tbase = (const char*)sT + k * 16;

#pragma unroll
    for (int it = 0; it < 4; ++it) {
        const float2 pk = sP[it * 64 + p];      // broadcast within 4-lane group
        const int   off = __float_as_int(pk.x);
        const float s   = pk.y;

        float4 v = *(const float4*)(tbase + off);

        // packed f32x2 multiplies: 2 instructions instead of 4
        uint64_t lo, hi, sv, rlo, rhi;
        asm("mov.b64 %0, {%1, %2};" : "=l"(sv) : "f"(s), "f"(s));
        asm("mov.b64 %0, {%1, %2};" : "=l"(lo) : "f"(v.x), "f"(v.y));
        asm("mov.b64 %0, {%1, %2};" : "=l"(hi) : "f"(v.z), "f"(v.w));
        asm("mul.rn.f32x2 %0, %1, %2;" : "=l"(rlo) : "l"(lo), "l"(sv));
        asm("mul.rn.f32x2 %0, %1, %2;" : "=l"(rhi) : "l"(hi), "l"(sv));
        float4 r;
        asm("mov.b64 {%0, %1}, %2;" : "=f"(r.x), "=f"(r.y) : "l"(rlo));
        asm("mov.b64 {%0, %1}, %2;" : "=f"(r.z), "=f"(r.w) : "l"(rhi));

        *(float4*)(optr + (size_t)it * 64 * TDIM) = r;
    }
}

// ---------------------------------------------------------------------------
// Launch: build table, then PDL-overlapped encode.
// ---------------------------------------------------------------------------
extern "C" void kernel_launch(void* const* d_in, const int* in_sizes, int n_in,
                              void* d_out, int out_size) {
    const float* coords = (const float*)d_in[0];  // (B,N,3)
    const float* conf   = (const float*)d_in[1];  // (B,N)
    const float* W      = (const float*)d_in[2];  // (22,16)
    const float* b      = (const float*)d_in[3];  // (16,)
    const float* gamma  = (const float*)d_in[4];  // (16,)
    const float* beta   = (const float*)d_in[5];  // (16,)
    float* out = (float*)d_out;                   // (B,N,N,16)

    build_table_kernel<<<1, 32>>>(W, b, gamma, beta);

    dim3 grid(NPTS / 256, NPTS, BATCH);

    cudaLaunchConfig_t cfg = {};
    cfg.gridDim  = grid;
    cfg.blockDim = dim3(256, 1, 1);
    cfg.dynamicSmemBytes = 0;
    cfg.stream = 0;
    cudaLaunchAttribute attr;
    attr.id = cudaLaunchAttributeProgrammaticStreamSerialization;
    attr.val.programmaticStreamSerializationAllowed = 1;
    cfg.attrs = &attr;
    cfg.numAttrs = 1;

    cudaError_t e = cudaLaunchKernelEx(&cfg, encode_kernel, coords, conf, out);
    if (e != cudaSuccess) {
        // PDL unavailable: plain serialized launch (still correct)
        encode_kernel<<<grid, 256>>>(coords, conf, out);
    }
}